// round 9
// baseline (speedup 1.0000x reference)
#include <cuda_runtime.h>
#include <math.h>

// Problem constants (fixed by setup_inputs)
#define BB 8
#define TT 600
#define CC 8
#define FF 257
#define NTAPS 5
#define NDELAY 3
#define KC 40           // NTAPS*CC
#define EPSV 1e-10f
#define NTHREADS 256
// valid frame count Tq = T - DELAY - TAPS + 1 = 593; u in [4, 597)

typedef unsigned long long u64;

// Scratch: Y and enhanced in (B,F,C,T) complex layout
__device__ float2 g_Y[(size_t)BB*FF*CC*TT];
__device__ float2 g_E[(size_t)BB*FF*CC*TT];

struct WpeSmem {
    float2 Y[CC][TT];          // 38400 B
    float  invp[TT];           //  2400 B  (dinv[KC] during LDL/solve)
    float  ps[TT];             //  2400 B  (|E1|^2 sum for iter-2 power)
    float2 R[KC][KC+1];        // 13120 B  (padded row)
    float2 P[NTAPS][CC][CC];   //  2560 B  [k][e][d]
    float2 G[NTAPS][CC][CC];   //  2560 B  [p][d][e]
};                             // total 61440 B -> 3 CTAs/SM

// ---------------- packed f32x2 helpers (sm_103a FFMA2 path) ----------------
__device__ __forceinline__ u64 pk2(float lo, float hi) {
    u64 r; asm("mov.b64 %0, {%1, %2};" : "=l"(r) : "f"(lo), "f"(hi)); return r;
}
__device__ __forceinline__ float2 upk2(u64 v) {
    float2 r; asm("mov.b64 {%0, %1}, %2;" : "=f"(r.x), "=f"(r.y) : "l"(v)); return r;
}
__device__ __forceinline__ u64 fma2(u64 a, u64 b, u64 c) {
    u64 d; asm("fma.rn.f32x2 %0, %1, %2, %3;" : "=l"(d) : "l"(a), "l"(b), "l"(c)); return d;
}
__device__ __forceinline__ u64 mul2(u64 a, u64 b) {
    u64 d; asm("mul.rn.f32x2 %0, %1, %2;" : "=l"(d) : "l"(a), "l"(b)); return d;
}
__device__ __forceinline__ float2 shfl2(float2 v, int src) {
    float2 r;
    r.x = __shfl_sync(0xffffffffu, v.x, src);
    r.y = __shfl_sync(0xffffffffu, v.y, src);
    return r;
}

// ---------------------------------------------------------------------------
// Transpose in: (B,T,C,F) real+imag planes -> g_Y (B,F,C,T) float2
// ---------------------------------------------------------------------------
__global__ void k_transpose_in(const float* __restrict__ re,
                               const float* __restrict__ im) {
    __shared__ float2 tile[32][33];
    int bc = blockIdx.z;
    int b = bc / CC, c = bc % CC;
    int f0 = blockIdx.x * 32, t0 = blockIdx.y * 32;
    int tx = threadIdx.x, ty = threadIdx.y;
#pragma unroll
    for (int j = 0; j < 4; j++) {
        int t = t0 + ty + j*8, f = f0 + tx;
        if (t < TT && f < FF) {
            size_t idx = ((size_t)(b*TT + t)*CC + c)*FF + f;
            tile[ty + j*8][tx] = make_float2(re[idx], im[idx]);
        }
    }
    __syncthreads();
#pragma unroll
    for (int j = 0; j < 4; j++) {
        int f = f0 + ty + j*8, t = t0 + tx;
        if (t < TT && f < FF) {
            g_Y[((size_t)(b*FF + f)*CC + c)*TT + t] = tile[tx][ty + j*8];
        }
    }
}

// ---------------------------------------------------------------------------
// Transpose out: g_E (B,F,C,T) -> out real/imag planes (B,T,C,F), masked
// ---------------------------------------------------------------------------
__global__ void k_transpose_out(float* __restrict__ out,
                                const int* __restrict__ ilens) {
    __shared__ float2 tile[32][33];
    int bc = blockIdx.z;
    int b = bc / CC, c = bc % CC;
    int t0 = blockIdx.x * 32, f0 = blockIdx.y * 32;
    int tx = threadIdx.x, ty = threadIdx.y;
    int ilen = ilens[b];
    const size_t N = (size_t)BB*TT*CC*FF;
#pragma unroll
    for (int j = 0; j < 4; j++) {
        int f = f0 + ty + j*8, t = t0 + tx;
        if (t < TT && f < FF) {
            tile[ty + j*8][tx] = g_E[((size_t)(b*FF + f)*CC + c)*TT + t];
        }
    }
    __syncthreads();
#pragma unroll
    for (int j = 0; j < 4; j++) {
        int t = t0 + ty + j*8, f = f0 + tx;
        if (t < TT && f < FF) {
            float2 v = tile[tx][ty + j*8];
            if (t >= ilen) v = make_float2(0.f, 0.f);
            size_t idx = ((size_t)(b*TT + t)*CC + c)*FF + f;
            out[idx]     = v.x;
            out[N + idx] = v.y;
        }
    }
}

// ---------------------------------------------------------------------------
// Fused WPE: one CTA per (b,f). 2 iterations entirely in shared memory.
// Occupancy 3: 61.4KB smem; reverb split in 2 passes to stay under 84 regs.
// ---------------------------------------------------------------------------
__global__ __launch_bounds__(NTHREADS, 3) void k_wpe() {
    extern __shared__ char smem_raw[];
    WpeSmem* s = (WpeSmem*)smem_raw;
    int bf = blockIdx.x;
    int tid = threadIdx.x;

    // Load Y (C,T) contiguously
    const float2* Yg = g_Y + (size_t)bf * CC * TT;
    float2* sYf = &s->Y[0][0];
    for (int i = tid; i < CC*TT; i += NTHREADS) sYf[i] = Yg[i];
    __syncthreads();

    for (int it = 0; it < 2; it++) {
        // ---- power -> invp ----
        if (it == 0) {
            for (int t = tid; t < TT; t += NTHREADS) {
                float sum = 0.f;
#pragma unroll
                for (int c = 0; c < CC; c++) {
                    float2 y = s->Y[c][t];
                    sum += y.x*y.x + y.y*y.y;
                }
                s->invp[t] = 1.0f / fmaxf(sum * (1.0f / CC), EPSV);
                s->ps[t] = 0.f;     // zero for iter-1 reverb accumulation
            }
        } else {
            for (int t = tid; t < TT; t += NTHREADS)
                s->invp[t] = 1.0f / fmaxf(s->ps[t] * (1.0f / CC), EPSV);
        }
        __syncthreads();

        // ---- fused R + P accumulation, single pass over full u range ----
        // R jobs: threads 0..179 = (pair d<=e [36], k [5]); full 593 u each.
        //   R[k*8+d][l*8+e] = sum_u conj(Y[d][u-k]) invp[u+3] Y[e][u-l]
        // P jobs: threads 192..255 = ordered pair (d,e) [64]; full 593 u.
        //   P[k][e][d] = sum_u conj(Y[d][u-k]) invp[u+3] Y[e][u+3]
        if (tid < 180) {
            int pair = tid / 5, k = tid % 5;
            int e = 0;
            while ((e+1)*(e+2)/2 <= pair) e++;
            int d = pair - e*(e+1)/2;            // d <= e
            u64 acc[NTAPS];
#pragma unroll
            for (int l = 0; l < NTAPS; l++) acc[l] = 0ull;
            u64 wep[NTAPS], wes[NTAPS];
#pragma unroll
            for (int l = 0; l < NTAPS-1; l++) {
                float2 y = s->Y[e][3 - l];
                wep[l] = pk2(y.x, y.y);
                wes[l] = pk2(y.y, y.x);
            }
            wep[NTAPS-1] = wes[NTAPS-1] = 0ull;
#pragma unroll 5
            for (int u = 4; u < 597; u++) {
#pragma unroll
                for (int l = NTAPS-1; l > 0; l--) { wep[l]=wep[l-1]; wes[l]=wes[l-1]; }
                float2 ye = s->Y[e][u];
                wep[0] = pk2(ye.x, ye.y);
                wes[0] = pk2(ye.y, ye.x);
                float2 yd = s->Y[d][u - k];
                float w = s->invp[u + 3];
                u64 ww = pk2(w, w);
                u64 aw  = mul2(ww, pk2(yd.x, yd.x));
                u64 awn = mul2(ww, pk2(yd.y, -yd.y));
#pragma unroll
                for (int l = 0; l < NTAPS; l++) {
                    acc[l] = fma2(aw,  wep[l], acc[l]);
                    acc[l] = fma2(awn, wes[l], acc[l]);
                }
            }
#pragma unroll
            for (int l = 0; l < NTAPS; l++) {
                float2 v = upk2(acc[l]);
                s->R[k*CC + d][l*CC + e] = v;
                if (d < e)
                    s->R[l*CC + e][k*CC + d] = make_float2(v.x, -v.y);
            }
        } else if (tid >= 192) {
            int pair = tid - 192;
            int d = pair & 7, e = pair >> 3;
            u64 accp[NTAPS];
#pragma unroll
            for (int k = 0; k < NTAPS; k++) accp[k] = 0ull;
            u64 dxx[NTAPS], dyn_[NTAPS];
#pragma unroll
            for (int k = 0; k < NTAPS-1; k++) {
                float2 yd = s->Y[d][3 - k];
                dxx[k]  = pk2(yd.x, yd.x);
                dyn_[k] = pk2(yd.y, -yd.y);
            }
            dxx[NTAPS-1] = dyn_[NTAPS-1] = 0ull;
#pragma unroll 5
            for (int u = 4; u < 597; u++) {
#pragma unroll
                for (int k = NTAPS-1; k > 0; k--) { dxx[k]=dxx[k-1]; dyn_[k]=dyn_[k-1]; }
                float2 yd = s->Y[d][u];
                dxx[0]  = pk2(yd.x, yd.x);
                dyn_[0] = pk2(yd.y, -yd.y);
                float w = s->invp[u + 3];
                u64 ww = pk2(w, w);
                float2 ye = s->Y[e][u + 3];
                u64 sv  = mul2(ww, pk2(ye.x, ye.y));
                u64 svs = mul2(ww, pk2(ye.y, ye.x));
#pragma unroll
                for (int k = 0; k < NTAPS; k++) {
                    accp[k] = fma2(dxx[k],  sv,  accp[k]);
                    accp[k] = fma2(dyn_[k], svs, accp[k]);
                }
            }
#pragma unroll
            for (int k = 0; k < NTAPS; k++)
                s->P[k][e][d] = upk2(accp[k]);
        }
        __syncthreads();

        // ---- regularize diag ----
        if (tid < KC) s->R[tid][tid].x += EPSV;

        // ---- in-place LDL^H of R: one barrier per column ----
        for (int j = 0; j < KC; j++) {
            __syncthreads();                 // column j fully updated (also covers EPSV)
            float djj = s->R[j][j].x;        // broadcast read
            float dinv = 1.0f / fmaxf(djj, 1e-30f);
            if (tid == 0) s->invp[j] = dinv;
            for (int i = j + 1 + (tid & 31); i < KC; i += 32) {
                float2 Aij = s->R[i][j];
                float2 Aw = make_float2(Aij.x * dinv, Aij.y * dinv);
                for (int l = j + 1 + (tid >> 5); l <= i; l += 8) {
                    float2 Alj = s->R[l][j];
                    s->R[i][l].x -= Aw.x*Alj.x + Aw.y*Alj.y;
                    s->R[i][l].y -= Aw.y*Alj.x - Aw.x*Alj.y;
                }
            }
        }
        __syncthreads();

        // ---- triangular solves in registers: warp e solves for channel e ----
        {
            int lane = tid & 31, e = tid >> 5;
            float2 x0, x1;
            { int i = lane;      x0 = s->P[i>>3][e][i&7]; }
            if (lane < 8) { int i = lane + 32; x1 = s->P[i>>3][e][i&7]; }
            else x1 = make_float2(0.f, 0.f);
            float dinv0 = s->invp[lane];
            float dinv1 = (lane < 8) ? s->invp[lane + 32] : 0.f;

            // forward: unit-lower L y = b
            for (int j = 0; j < KC; j++) {
                int src = j & 31;
                float2 xj = (j < 32) ? shfl2(x0, src) : shfl2(x1, src);
                float dj = s->invp[j];
                float2 t = make_float2(xj.x * dj, xj.y * dj);
                if (lane > j) {
                    float2 L = s->R[lane][j];
                    x0.x -= L.x*t.x - L.y*t.y;
                    x0.y -= L.x*t.y + L.y*t.x;
                }
                if (lane < 8 && lane + 32 > j) {
                    float2 L = s->R[lane+32][j];
                    x1.x -= L.x*t.x - L.y*t.y;
                    x1.y -= L.x*t.y + L.y*t.x;
                }
            }
            // z = D^{-1} y
            x0.x *= dinv0; x0.y *= dinv0;
            x1.x *= dinv1; x1.y *= dinv1;
            // backward: L^H x = z
            for (int j = KC - 1; j >= 1; j--) {
                int src = j & 31;
                float2 xj = (j < 32) ? shfl2(x0, src) : shfl2(x1, src);
                if (lane < j) {
                    float2 A = s->R[j][lane];
                    x0.x -= dinv0 * (A.x*xj.x + A.y*xj.y);
                    x0.y -= dinv0 * (A.x*xj.y - A.y*xj.x);
                }
                if (lane < 8 && lane + 32 < j) {
                    float2 A = s->R[j][lane+32];
                    x1.x -= dinv1 * (A.x*xj.x + A.y*xj.y);
                    x1.y -= dinv1 * (A.x*xj.y - A.y*xj.x);
                }
            }
            // write G_conj: i=(k*8+d) -> G[k][d][e]
            { int i = lane;      s->G[i>>3][i&7][e] = x0; }
            if (lane < 8) { int i = lane + 32; s->G[i>>3][i&7][e] = x1; }
        }
        __syncthreads();

        // ---- reverb: E[e][t] = Y[e][t] - sum_{p,d} G[p][d][e] * Y[d][t-3-p] ----
        // lane owns 19 contiguous frames, processed in 2 passes (10+9) to cap
        // live registers (acc[10]) under the occupancy-3 budget.
        // iter-1: accumulate |E|^2 into ps (Y untouched).
        // iter-2: store E straight to g_E from registers (no smem staging).
        {
            int lane = tid & 31, e = tid >> 5;
            int t0 = lane * 19;
            float2* Eg = g_E + ((size_t)bf * CC + e) * TT;
#pragma unroll
            for (int pass = 0; pass < 2; pass++) {
                const int NF = (pass == 0) ? 10 : 9;
                const int tb = t0 + pass * 10;
                u64 acc[10];
#pragma unroll
                for (int i = 0; i < NF; i++) {
                    int t = tb + i;
                    float2 y = s->Y[e][t < TT ? t : TT-1];
                    acc[i] = pk2(y.x, y.y);
                }
#pragma unroll
                for (int d = 0; d < CC; d++) {
                    u64 gxn[NTAPS], gys[NTAPS];
#pragma unroll
                    for (int p = 0; p < NTAPS; p++) {
                        float2 g = s->G[p][d][e];    // broadcast LDS
                        gxn[p] = pk2(-g.x, -g.x);
                        gys[p] = pk2(g.y, -g.y);
                    }
                    u64 w[NTAPS], ws[NTAPS];
#pragma unroll
                    for (int p = 0; p < NTAPS-1; p++) {
                        int tt = tb - 4 - p;
                        float2 y = (tt >= 0) ? s->Y[d][tt] : make_float2(0.f, 0.f);
                        w[p]  = pk2(y.x, y.y);
                        ws[p] = pk2(y.y, y.x);
                    }
                    w[NTAPS-1] = ws[NTAPS-1] = 0ull;
#pragma unroll
                    for (int i = 0; i < NF; i++) {
                        int t = tb + i;
#pragma unroll
                        for (int p = NTAPS-1; p > 0; p--) { w[p]=w[p-1]; ws[p]=ws[p-1]; }
                        float2 y = (t >= 3 && t < TT) ? s->Y[d][t-3]
                                                      : make_float2(0.f, 0.f);
                        w[0]  = pk2(y.x, y.y);
                        ws[0] = pk2(y.y, y.x);
#pragma unroll
                        for (int p = 0; p < NTAPS; p++) {
                            acc[i] = fma2(gxn[p], w[p],  acc[i]);
                            acc[i] = fma2(gys[p], ws[p], acc[i]);
                        }
                    }
                }
                if (it == 0) {
#pragma unroll
                    for (int i = 0; i < NF; i++) {
                        int t = tb + i;
                        if (t < TT) {
                            float2 v = upk2(acc[i]);
                            atomicAdd(&s->ps[t], v.x*v.x + v.y*v.y);
                        }
                    }
                } else {
#pragma unroll
                    for (int i = 0; i < NF; i++) {
                        int t = tb + i;
                        if (t < TT) Eg[t] = upk2(acc[i]);
                    }
                }
            }
            if (it == 0) __syncthreads();   // ps complete before iter-2 power
        }
    } // iterations
}

// ---------------------------------------------------------------------------
extern "C" void kernel_launch(void* const* d_in, const int* in_sizes, int n_in,
                              void* d_out, int out_size) {
    const float* re    = (const float*)d_in[0];
    const float* im    = (const float*)d_in[1];
    const int*   ilens = (const int*)d_in[2];
    float* out = (float*)d_out;

    cudaFuncSetAttribute(k_wpe, cudaFuncAttributeMaxDynamicSharedMemorySize,
                         (int)sizeof(WpeSmem));

    dim3 blk(32, 8);
    k_transpose_in<<<dim3((FF+31)/32, (TT+31)/32, BB*CC), blk>>>(re, im);
    k_wpe<<<BB*FF, NTHREADS, sizeof(WpeSmem)>>>();
    k_transpose_out<<<dim3((TT+31)/32, (FF+31)/32, BB*CC), blk>>>(out, ilens);
}

// round 10
// speedup vs baseline: 1.0154x; 1.0154x over previous
#include <cuda_runtime.h>
#include <math.h>

// Problem constants (fixed by setup_inputs)
#define BB 8
#define TT 600
#define CC 8
#define FF 257
#define NTAPS 5
#define NDELAY 3
#define KC 40           // NTAPS*CC
#define EPSV 1e-10f
#define NTHREADS 256
// valid frame count Tq = T - DELAY - TAPS + 1 = 593; u in [4, 597)

// Padded Y row: 8 leading zeros + 600 data + 9 trailing zeros = 617 float2.
// 617*2 = 1234 ≡ 18 (mod 32) banks -> all 8 channel rows on distinct banks.
#define TP 617
#define TOFF 8

typedef unsigned long long u64;

// Scratch: Y and enhanced in (B,F,C,T) complex layout
__device__ float2 g_Y[(size_t)BB*FF*CC*TT];
__device__ float2 g_E[(size_t)BB*FF*CC*TT];

struct WpeSmem {
    float2 Y[CC][TP];          // 39488 B  (zero-padded both ends)
    float  invp[TT];           //  2400 B  (weights during R/P; ps after)
    float2 R[KC][KC+1];        // 13120 B  (padded row; dinv lives in diag .y)
    float2 P[NTAPS][CC][CC];   //  2560 B  [k][e][d]
    float2 G[NTAPS][CC][CC];   //  2560 B  [p][d][e]
};                             // total 60128 B -> 3 CTAs/SM

// ---------------- packed f32x2 helpers (sm_103a FFMA2 path) ----------------
__device__ __forceinline__ u64 pk2(float lo, float hi) {
    u64 r; asm("mov.b64 %0, {%1, %2};" : "=l"(r) : "f"(lo), "f"(hi)); return r;
}
__device__ __forceinline__ float2 upk2(u64 v) {
    float2 r; asm("mov.b64 {%0, %1}, %2;" : "=f"(r.x), "=f"(r.y) : "l"(v)); return r;
}
__device__ __forceinline__ u64 fma2(u64 a, u64 b, u64 c) {
    u64 d; asm("fma.rn.f32x2 %0, %1, %2, %3;" : "=l"(d) : "l"(a), "l"(b), "l"(c)); return d;
}
__device__ __forceinline__ u64 mul2(u64 a, u64 b) {
    u64 d; asm("mul.rn.f32x2 %0, %1, %2;" : "=l"(d) : "l"(a), "l"(b)); return d;
}
__device__ __forceinline__ float2 shfl2(float2 v, int src) {
    float2 r;
    r.x = __shfl_sync(0xffffffffu, v.x, src);
    r.y = __shfl_sync(0xffffffffu, v.y, src);
    return r;
}

// ---------------------------------------------------------------------------
// Transpose in: (B,T,C,F) real+imag planes -> g_Y (B,F,C,T) float2
// ---------------------------------------------------------------------------
__global__ void k_transpose_in(const float* __restrict__ re,
                               const float* __restrict__ im) {
    __shared__ float2 tile[32][33];
    int bc = blockIdx.z;
    int b = bc / CC, c = bc % CC;
    int f0 = blockIdx.x * 32, t0 = blockIdx.y * 32;
    int tx = threadIdx.x, ty = threadIdx.y;
#pragma unroll
    for (int j = 0; j < 4; j++) {
        int t = t0 + ty + j*8, f = f0 + tx;
        if (t < TT && f < FF) {
            size_t idx = ((size_t)(b*TT + t)*CC + c)*FF + f;
            tile[ty + j*8][tx] = make_float2(re[idx], im[idx]);
        }
    }
    __syncthreads();
#pragma unroll
    for (int j = 0; j < 4; j++) {
        int f = f0 + ty + j*8, t = t0 + tx;
        if (t < TT && f < FF) {
            g_Y[((size_t)(b*FF + f)*CC + c)*TT + t] = tile[tx][ty + j*8];
        }
    }
}

// ---------------------------------------------------------------------------
// Transpose out: g_E (B,F,C,T) -> out real/imag planes (B,T,C,F), masked
// ---------------------------------------------------------------------------
__global__ void k_transpose_out(float* __restrict__ out,
                                const int* __restrict__ ilens) {
    __shared__ float2 tile[32][33];
    int bc = blockIdx.z;
    int b = bc / CC, c = bc % CC;
    int t0 = blockIdx.x * 32, f0 = blockIdx.y * 32;
    int tx = threadIdx.x, ty = threadIdx.y;
    int ilen = ilens[b];
    const size_t N = (size_t)BB*TT*CC*FF;
#pragma unroll
    for (int j = 0; j < 4; j++) {
        int f = f0 + ty + j*8, t = t0 + tx;
        if (t < TT && f < FF) {
            tile[ty + j*8][tx] = g_E[((size_t)(b*FF + f)*CC + c)*TT + t];
        }
    }
    __syncthreads();
#pragma unroll
    for (int j = 0; j < 4; j++) {
        int t = t0 + ty + j*8, f = f0 + tx;
        if (t < TT && f < FF) {
            float2 v = tile[tx][ty + j*8];
            if (t >= ilen) v = make_float2(0.f, 0.f);
            size_t idx = ((size_t)(b*TT + t)*CC + c)*FF + f;
            out[idx]     = v.x;
            out[N + idx] = v.y;
        }
    }
}

// ---------------------------------------------------------------------------
// Fused WPE: one CTA per (b,f). 2 iterations entirely in shared memory.
// ---------------------------------------------------------------------------
__global__ __launch_bounds__(NTHREADS, 3) void k_wpe() {
    extern __shared__ char smem_raw[];
    WpeSmem* s = (WpeSmem*)smem_raw;
    int bf = blockIdx.x;
    int tid = threadIdx.x;

    // Load Y rows into padded smem; zero the pads.
    const float2* Yg = g_Y + (size_t)bf * CC * TT;
#pragma unroll
    for (int c = 0; c < CC; c++)
        for (int t = tid; t < TT; t += NTHREADS)
            s->Y[c][t + TOFF] = Yg[c*TT + t];
    if (tid < CC * 17) {                 // 8 front + 9 back pads per row
        int c = tid / 17, p = tid % 17;
        int idx = (p < TOFF) ? p : (TT + p);   // 0..7 and 608..616
        s->Y[c][idx] = make_float2(0.f, 0.f);
    }
    __syncthreads();

    for (int it = 0; it < 2; it++) {
        // ---- power -> invp ----
        if (it == 0) {
            for (int t = tid; t < TT; t += NTHREADS) {
                float sum = 0.f;
#pragma unroll
                for (int c = 0; c < CC; c++) {
                    float2 y = s->Y[c][t + TOFF];
                    sum += y.x*y.x + y.y*y.y;
                }
                s->invp[t] = 1.0f / fmaxf(sum * (1.0f / CC), EPSV);
            }
        } else {
            // invp currently holds ps (|E1|^2 sums); convert in place
            for (int t = tid; t < TT; t += NTHREADS)
                s->invp[t] = 1.0f / fmaxf(s->invp[t] * (1.0f / CC), EPSV);
        }
        __syncthreads();

        // ---- fused R + P accumulation, single pass over full u range ----
        // R jobs: threads 0..179 = (pair d<=e [36], k [5]); full 593 u each.
        // P jobs: threads 192..255 = ordered pair (d,e) [64]; full 593 u.
        if (tid < 180) {
            int pair = tid / 5, k = tid % 5;
            int e = 0;
            while ((e+1)*(e+2)/2 <= pair) e++;
            int d = pair - e*(e+1)/2;            // d <= e
            u64 acc[NTAPS];
#pragma unroll
            for (int l = 0; l < NTAPS; l++) acc[l] = 0ull;
            u64 wep[NTAPS], wes[NTAPS];
#pragma unroll
            for (int l = 0; l < NTAPS-1; l++) {
                float2 y = s->Y[e][3 - l + TOFF];
                wep[l] = pk2(y.x, y.y);
                wes[l] = pk2(y.y, y.x);
            }
            wep[NTAPS-1] = wes[NTAPS-1] = 0ull;
#pragma unroll 5
            for (int u = 4; u < 597; u++) {
#pragma unroll
                for (int l = NTAPS-1; l > 0; l--) { wep[l]=wep[l-1]; wes[l]=wes[l-1]; }
                float2 ye = s->Y[e][u + TOFF];
                wep[0] = pk2(ye.x, ye.y);
                wes[0] = pk2(ye.y, ye.x);
                float2 yd = s->Y[d][u - k + TOFF];
                float w = s->invp[u + 3];
                u64 ww = pk2(w, w);
                u64 aw  = mul2(ww, pk2(yd.x, yd.x));
                u64 awn = mul2(ww, pk2(yd.y, -yd.y));
#pragma unroll
                for (int l = 0; l < NTAPS; l++) {
                    acc[l] = fma2(aw,  wep[l], acc[l]);
                    acc[l] = fma2(awn, wes[l], acc[l]);
                }
            }
#pragma unroll
            for (int l = 0; l < NTAPS; l++) {
                float2 v = upk2(acc[l]);
                s->R[k*CC + d][l*CC + e] = v;
                if (d < e)
                    s->R[l*CC + e][k*CC + d] = make_float2(v.x, -v.y);
            }
        } else if (tid >= 192) {
            int pair = tid - 192;
            int d = pair & 7, e = pair >> 3;
            u64 accp[NTAPS];
#pragma unroll
            for (int k = 0; k < NTAPS; k++) accp[k] = 0ull;
            u64 dxx[NTAPS], dyn_[NTAPS];
#pragma unroll
            for (int k = 0; k < NTAPS-1; k++) {
                float2 yd = s->Y[d][3 - k + TOFF];
                dxx[k]  = pk2(yd.x, yd.x);
                dyn_[k] = pk2(yd.y, -yd.y);
            }
            dxx[NTAPS-1] = dyn_[NTAPS-1] = 0ull;
#pragma unroll 5
            for (int u = 4; u < 597; u++) {
#pragma unroll
                for (int k = NTAPS-1; k > 0; k--) { dxx[k]=dxx[k-1]; dyn_[k]=dyn_[k-1]; }
                float2 yd = s->Y[d][u + TOFF];
                dxx[0]  = pk2(yd.x, yd.x);
                dyn_[0] = pk2(yd.y, -yd.y);
                float w = s->invp[u + 3];
                u64 ww = pk2(w, w);
                float2 ye = s->Y[e][u + 3 + TOFF];
                u64 sv  = mul2(ww, pk2(ye.x, ye.y));
                u64 svs = mul2(ww, pk2(ye.y, ye.x));
#pragma unroll
                for (int k = 0; k < NTAPS; k++) {
                    accp[k] = fma2(dxx[k],  sv,  accp[k]);
                    accp[k] = fma2(dyn_[k], svs, accp[k]);
                }
            }
#pragma unroll
            for (int k = 0; k < NTAPS; k++)
                s->P[k][e][d] = upk2(accp[k]);
        }
        __syncthreads();

        // ---- weights dead: repurpose invp as ps accumulator (zero it);
        //      regularize R diag. Both covered by LDL's first barrier. ----
        for (int t = tid; t < TT; t += NTHREADS) s->invp[t] = 0.f;
        if (tid < KC) s->R[tid][tid].x += EPSV;

        // ---- in-place LDL^H of R: one barrier per column; dinv -> R[j][j].y
        for (int j = 0; j < KC; j++) {
            __syncthreads();                 // column j fully updated
            float djj = s->R[j][j].x;        // broadcast read
            float dinv = 1.0f / fmaxf(djj, 1e-30f);
            if (tid == 0) s->R[j][j].y = dinv;
            for (int i = j + 1 + (tid & 31); i < KC; i += 32) {
                float2 Aij = s->R[i][j];
                float2 Aw = make_float2(Aij.x * dinv, Aij.y * dinv);
                for (int l = j + 1 + (tid >> 5); l <= i; l += 8) {
                    float2 Alj = s->R[l][j];
                    s->R[i][l].x -= Aw.x*Alj.x + Aw.y*Alj.y;
                    s->R[i][l].y -= Aw.y*Alj.x - Aw.x*Alj.y;
                }
            }
        }
        __syncthreads();

        // ---- triangular solves in registers: warp e solves for channel e ----
        {
            int lane = tid & 31, e = tid >> 5;
            float2 x0, x1;
            { int i = lane;      x0 = s->P[i>>3][e][i&7]; }
            if (lane < 8) { int i = lane + 32; x1 = s->P[i>>3][e][i&7]; }
            else x1 = make_float2(0.f, 0.f);
            float dinv0 = s->R[lane][lane].y;
            float dinv1 = (lane < 8) ? s->R[lane+32][lane+32].y : 0.f;

            // forward: unit-lower L y = b
            for (int j = 0; j < KC; j++) {
                int src = j & 31;
                float2 xj = (j < 32) ? shfl2(x0, src) : shfl2(x1, src);
                float dj = s->R[j][j].y;
                float2 t = make_float2(xj.x * dj, xj.y * dj);
                if (lane > j) {
                    float2 L = s->R[lane][j];
                    x0.x -= L.x*t.x - L.y*t.y;
                    x0.y -= L.x*t.y + L.y*t.x;
                }
                if (lane < 8 && lane + 32 > j) {
                    float2 L = s->R[lane+32][j];
                    x1.x -= L.x*t.x - L.y*t.y;
                    x1.y -= L.x*t.y + L.y*t.x;
                }
            }
            // z = D^{-1} y
            x0.x *= dinv0; x0.y *= dinv0;
            x1.x *= dinv1; x1.y *= dinv1;
            // backward: L^H x = z
            for (int j = KC - 1; j >= 1; j--) {
                int src = j & 31;
                float2 xj = (j < 32) ? shfl2(x0, src) : shfl2(x1, src);
                if (lane < j) {
                    float2 A = s->R[j][lane];
                    x0.x -= dinv0 * (A.x*xj.x + A.y*xj.y);
                    x0.y -= dinv0 * (A.x*xj.y - A.y*xj.x);
                }
                if (lane < 8 && lane + 32 < j) {
                    float2 A = s->R[j][lane+32];
                    x1.x -= dinv1 * (A.x*xj.x + A.y*xj.y);
                    x1.y -= dinv1 * (A.x*xj.y - A.y*xj.x);
                }
            }
            // write G_conj: i=(k*8+d) -> G[k][d][e]
            { int i = lane;      s->G[i>>3][i&7][e] = x0; }
            if (lane < 8) { int i = lane + 32; s->G[i>>3][i&7][e] = x1; }
        }
        __syncthreads();

        // ---- reverb: E[e][t] = Y[e][t] - sum_{p,d} G[p][d][e] * Y[d][t-3-p] ----
        // single-pass 19 frames/lane; padded Y -> NO load guards.
        // iter-1: accumulate |E|^2 into invp (ps). iter-2: store E to g_E.
        {
            int lane = tid & 31, e = tid >> 5;
            int t0 = lane * 19;
            float2* Eg = g_E + ((size_t)bf * CC + e) * TT;
            u64 acc[19];
#pragma unroll
            for (int i = 0; i < 19; i++) {
                float2 y = s->Y[e][t0 + i + TOFF];   // pad reads give zeros
                acc[i] = pk2(y.x, y.y);
            }
#pragma unroll
            for (int d = 0; d < CC; d++) {
                u64 gxn[NTAPS], gys[NTAPS];
#pragma unroll
                for (int p = 0; p < NTAPS; p++) {
                    float2 g = s->G[p][d][e];        // broadcast LDS
                    gxn[p] = pk2(-g.x, -g.x);
                    gys[p] = pk2(g.y, -g.y);
                }
                u64 w[NTAPS], ws[NTAPS];
#pragma unroll
                for (int p = 0; p < NTAPS-1; p++) {
                    float2 y = s->Y[d][t0 - 4 - p + TOFF];  // >= index 1, pad-safe
                    w[p]  = pk2(y.x, y.y);
                    ws[p] = pk2(y.y, y.x);
                }
                w[NTAPS-1] = ws[NTAPS-1] = 0ull;
#pragma unroll
                for (int i = 0; i < 19; i++) {
#pragma unroll
                    for (int p = NTAPS-1; p > 0; p--) { w[p]=w[p-1]; ws[p]=ws[p-1]; }
                    float2 y = s->Y[d][t0 + i - 3 + TOFF];  // pad-safe both ends
                    w[0]  = pk2(y.x, y.y);
                    ws[0] = pk2(y.y, y.x);
#pragma unroll
                    for (int p = 0; p < NTAPS; p++) {
                        acc[i] = fma2(gxn[p], w[p],  acc[i]);
                        acc[i] = fma2(gys[p], ws[p], acc[i]);
                    }
                }
            }
            if (it == 0) {
#pragma unroll
                for (int i = 0; i < 19; i++) {
                    int t = t0 + i;
                    if (t < TT) {
                        float2 v = upk2(acc[i]);
                        atomicAdd(&s->invp[t], v.x*v.x + v.y*v.y);
                    }
                }
                __syncthreads();    // ps complete before iter-2 power
            } else {
#pragma unroll
                for (int i = 0; i < 19; i++) {
                    int t = t0 + i;
                    if (t < TT) Eg[t] = upk2(acc[i]);
                }
            }
        }
    } // iterations
}

// ---------------------------------------------------------------------------
extern "C" void kernel_launch(void* const* d_in, const int* in_sizes, int n_in,
                              void* d_out, int out_size) {
    const float* re    = (const float*)d_in[0];
    const float* im    = (const float*)d_in[1];
    const int*   ilens = (const int*)d_in[2];
    float* out = (float*)d_out;

    cudaFuncSetAttribute(k_wpe, cudaFuncAttributeMaxDynamicSharedMemorySize,
                         (int)sizeof(WpeSmem));

    dim3 blk(32, 8);
    k_transpose_in<<<dim3((FF+31)/32, (TT+31)/32, BB*CC), blk>>>(re, im);
    k_wpe<<<BB*FF, NTHREADS, sizeof(WpeSmem)>>>();
    k_transpose_out<<<dim3((TT+31)/32, (FF+31)/32, BB*CC), blk>>>(out, ilens);
}

// round 11
// speedup vs baseline: 1.1583x; 1.1407x over previous
#include <cuda_runtime.h>
#include <math.h>

// Problem constants (fixed by setup_inputs)
#define BB 8
#define TT 600
#define CC 8
#define FF 257
#define NTAPS 5
#define NDELAY 3
#define KC 40           // NTAPS*CC
#define EPSV 1e-10f
#define NTHREADS 256
// valid frame count Tq = T - DELAY - TAPS + 1 = 593; u in [4, 597)

// Padded Y row: 8 leading zeros + 600 data + 10 trailing zeros = 618 float2.
// Row stride 618*8 B: 16B-aligned rows (float4 loads OK); bank offsets between
// rows = 20 mod 32 -> all 8 channel rows on distinct banks.
#define TP 618
#define TOFF 8
#define IOFF 1          // invp values at [IOFF+t] so invp[IOFF+u+3] is 16B-aligned

typedef unsigned long long u64;

// Scratch: Y and enhanced in (B,F,C,T) complex layout
__device__ float2 g_Y[(size_t)BB*FF*CC*TT];
__device__ float2 g_E[(size_t)BB*FF*CC*TT];

struct WpeSmem {
    float2 Y[CC][TP];          // 39552 B  (zero-padded both ends)
    float  invp[604];          //  2416 B  (weights during R/P; ps after)
    float2 R[KC][KC+1];        // 13120 B  (padded row; dinv lives in diag .y)
    float2 P[NTAPS][CC][CC];   //  2560 B  [k][e][d]
    float2 G[NTAPS][CC][CC];   //  2560 B  [p][d][e]
};                             // total 60208 B -> 3 CTAs/SM

// ---------------- packed f32x2 helpers (sm_103a FFMA2 path) ----------------
__device__ __forceinline__ u64 pk2(float lo, float hi) {
    u64 r; asm("mov.b64 %0, {%1, %2};" : "=l"(r) : "f"(lo), "f"(hi)); return r;
}
__device__ __forceinline__ float2 upk2(u64 v) {
    float2 r; asm("mov.b64 {%0, %1}, %2;" : "=f"(r.x), "=f"(r.y) : "l"(v)); return r;
}
__device__ __forceinline__ u64 fma2(u64 a, u64 b, u64 c) {
    u64 d; asm("fma.rn.f32x2 %0, %1, %2, %3;" : "=l"(d) : "l"(a), "l"(b), "l"(c)); return d;
}
__device__ __forceinline__ u64 mul2(u64 a, u64 b) {
    u64 d; asm("mul.rn.f32x2 %0, %1, %2;" : "=l"(d) : "l"(a), "l"(b)); return d;
}
__device__ __forceinline__ float2 shfl2(float2 v, int src) {
    float2 r;
    r.x = __shfl_sync(0xffffffffu, v.x, src);
    r.y = __shfl_sync(0xffffffffu, v.y, src);
    return r;
}

// ---------------------------------------------------------------------------
// Transpose in: (B,T,C,F) real+imag planes -> g_Y (B,F,C,T) float2
// ---------------------------------------------------------------------------
__global__ void k_transpose_in(const float* __restrict__ re,
                               const float* __restrict__ im) {
    __shared__ float2 tile[32][33];
    int bc = blockIdx.z;
    int b = bc / CC, c = bc % CC;
    int f0 = blockIdx.x * 32, t0 = blockIdx.y * 32;
    int tx = threadIdx.x, ty = threadIdx.y;
#pragma unroll
    for (int j = 0; j < 4; j++) {
        int t = t0 + ty + j*8, f = f0 + tx;
        if (t < TT && f < FF) {
            size_t idx = ((size_t)(b*TT + t)*CC + c)*FF + f;
            tile[ty + j*8][tx] = make_float2(re[idx], im[idx]);
        }
    }
    __syncthreads();
#pragma unroll
    for (int j = 0; j < 4; j++) {
        int f = f0 + ty + j*8, t = t0 + tx;
        if (t < TT && f < FF) {
            g_Y[((size_t)(b*FF + f)*CC + c)*TT + t] = tile[tx][ty + j*8];
        }
    }
}

// ---------------------------------------------------------------------------
// Transpose out: g_E (B,F,C,T) -> out real/imag planes (B,T,C,F), masked
// ---------------------------------------------------------------------------
__global__ void k_transpose_out(float* __restrict__ out,
                                const int* __restrict__ ilens) {
    __shared__ float2 tile[32][33];
    int bc = blockIdx.z;
    int b = bc / CC, c = bc % CC;
    int t0 = blockIdx.x * 32, f0 = blockIdx.y * 32;
    int tx = threadIdx.x, ty = threadIdx.y;
    int ilen = ilens[b];
    const size_t N = (size_t)BB*TT*CC*FF;
#pragma unroll
    for (int j = 0; j < 4; j++) {
        int f = f0 + ty + j*8, t = t0 + tx;
        if (t < TT && f < FF) {
            tile[ty + j*8][tx] = g_E[((size_t)(b*FF + f)*CC + c)*TT + t];
        }
    }
    __syncthreads();
#pragma unroll
    for (int j = 0; j < 4; j++) {
        int t = t0 + ty + j*8, f = f0 + tx;
        if (t < TT && f < FF) {
            float2 v = tile[tx][ty + j*8];
            if (t >= ilen) v = make_float2(0.f, 0.f);
            size_t idx = ((size_t)(b*TT + t)*CC + c)*FF + f;
            out[idx]     = v.x;
            out[N + idx] = v.y;
        }
    }
}

// ---------------------------------------------------------------------------
// Fused WPE: one CTA per (b,f). 2 iterations entirely in shared memory.
// ---------------------------------------------------------------------------
__global__ __launch_bounds__(NTHREADS, 3) void k_wpe() {
    extern __shared__ char smem_raw[];
    WpeSmem* s = (WpeSmem*)smem_raw;
    int bf = blockIdx.x;
    int tid = threadIdx.x;

    // Load Y rows into padded smem; zero the pads.
    const float2* Yg = g_Y + (size_t)bf * CC * TT;
#pragma unroll
    for (int c = 0; c < CC; c++)
        for (int t = tid; t < TT; t += NTHREADS)
            s->Y[c][t + TOFF] = Yg[c*TT + t];
    if (tid < CC * 18) {                 // 8 front + 10 back pads per row
        int c = tid / 18, p = tid % 18;
        int idx = (p < TOFF) ? p : (TT + p);   // 0..7 and 608..617
        s->Y[c][idx] = make_float2(0.f, 0.f);
    }
    __syncthreads();

    for (int it = 0; it < 2; it++) {
        // ---- power -> invp ----
        if (it == 0) {
            for (int t = tid; t < TT; t += NTHREADS) {
                float sum = 0.f;
#pragma unroll
                for (int c = 0; c < CC; c++) {
                    float2 y = s->Y[c][t + TOFF];
                    sum += y.x*y.x + y.y*y.y;
                }
                s->invp[t + IOFF] = 1.0f / fmaxf(sum * (1.0f / CC), EPSV);
            }
        } else {
            // invp currently holds ps (|E1|^2 sums); convert in place
            for (int t = tid; t < TT; t += NTHREADS)
                s->invp[t + IOFF] =
                    1.0f / fmaxf(s->invp[t + IOFF] * (1.0f / CC), EPSV);
        }
        __syncthreads();

        // ---- fused R + P accumulation, single pass over full u range ----
        // Split-accumulator scheme: for conj(c)*z with weight w,
        //   accA += (w*cx, w*cx) (x) (zx, zy);  accB += (w*cy, w*cy) (x) (zx, zy)
        //   re = A.lo + B.hi ;  im = A.hi - B.lo
        // R jobs: threads 0..179 = (pair d<=e [36], k [5]).
        // P jobs: threads 192..255 = ordered pair (d,e) [64].
        if (tid < 180) {
            int pair = tid / 5, k = tid % 5;
            int e = 0;
            while ((e+1)*(e+2)/2 <= pair) e++;
            int d = pair - e*(e+1)/2;            // d <= e
            u64 accA[NTAPS], accB[NTAPS];
#pragma unroll
            for (int l = 0; l < NTAPS; l++) { accA[l] = 0ull; accB[l] = 0ull; }
            u64 wep[NTAPS];                      // wep[l] = Ye[u-1-l] pack (x,y)
#pragma unroll
            for (int l = 0; l < NTAPS-1; l++) {
                float2 y = s->Y[e][3 - l + TOFF];
                wep[l] = pk2(y.x, y.y);
            }
            wep[NTAPS-1] = 0ull;

            auto stepR = [&](float w, float yex, float yey) {
#pragma unroll
                for (int l = NTAPS-1; l > 0; l--) wep[l] = wep[l-1];
                wep[0] = pk2(yex, yey);
                // yd loaded by caller? no: load here with current u via capture
            };
            (void)stepR;

            for (int u = 4; u < 596; u += 4) {
                float4 w4  = *reinterpret_cast<const float4*>(&s->invp[IOFF + u + 3]);
                float4 yeA = *reinterpret_cast<const float4*>(&s->Y[e][u + TOFF]);
                float4 yeB = *reinterpret_cast<const float4*>(&s->Y[e][u + 2 + TOFF]);
                float wj[4]  = {w4.x, w4.y, w4.z, w4.w};
                float yex[4] = {yeA.x, yeA.z, yeB.x, yeB.z};
                float yey[4] = {yeA.y, yeA.w, yeB.y, yeB.w};
#pragma unroll
                for (int j = 0; j < 4; j++) {
#pragma unroll
                    for (int l = NTAPS-1; l > 0; l--) wep[l] = wep[l-1];
                    wep[0] = pk2(yex[j], yey[j]);
                    float2 yd = s->Y[d][u + j - k + TOFF];
                    u64 ww = pk2(wj[j], wj[j]);
                    u64 aw = mul2(ww, pk2(yd.x, yd.x));
                    u64 bw = mul2(ww, pk2(yd.y, yd.y));
#pragma unroll
                    for (int l = 0; l < NTAPS; l++) {
                        accA[l] = fma2(aw, wep[l], accA[l]);
                        accB[l] = fma2(bw, wep[l], accB[l]);
                    }
                }
            }
            {   // remainder u = 596
                const int u = 596;
#pragma unroll
                for (int l = NTAPS-1; l > 0; l--) wep[l] = wep[l-1];
                float2 ye = s->Y[e][u + TOFF];
                wep[0] = pk2(ye.x, ye.y);
                float2 yd = s->Y[d][u - k + TOFF];
                float w = s->invp[IOFF + u + 3];
                u64 ww = pk2(w, w);
                u64 aw = mul2(ww, pk2(yd.x, yd.x));
                u64 bw = mul2(ww, pk2(yd.y, yd.y));
#pragma unroll
                for (int l = 0; l < NTAPS; l++) {
                    accA[l] = fma2(aw, wep[l], accA[l]);
                    accB[l] = fma2(bw, wep[l], accB[l]);
                }
            }
#pragma unroll
            for (int l = 0; l < NTAPS; l++) {
                float2 A = upk2(accA[l]), B = upk2(accB[l]);
                float2 v = make_float2(A.x + B.y, A.y - B.x);
                s->R[k*CC + d][l*CC + e] = v;
                if (d < e)
                    s->R[l*CC + e][k*CC + d] = make_float2(v.x, -v.y);
            }
        } else if (tid >= 192) {
            int pair = tid - 192;
            int d = pair & 7, e = pair >> 3;
            u64 accA[NTAPS], accB[NTAPS];
#pragma unroll
            for (int k = 0; k < NTAPS; k++) { accA[k] = 0ull; accB[k] = 0ull; }
            u64 dxx[NTAPS], dyy[NTAPS];          // window of Yd[u-k] broadcast packs
#pragma unroll
            for (int k = 0; k < NTAPS-1; k++) {
                float2 yd = s->Y[d][3 - k + TOFF];
                dxx[k] = pk2(yd.x, yd.x);
                dyy[k] = pk2(yd.y, yd.y);
            }
            dxx[NTAPS-1] = dyy[NTAPS-1] = 0ull;

            for (int u = 4; u < 596; u += 4) {
                float4 w4  = *reinterpret_cast<const float4*>(&s->invp[IOFF + u + 3]);
                float4 ydA = *reinterpret_cast<const float4*>(&s->Y[d][u + TOFF]);
                float4 ydB = *reinterpret_cast<const float4*>(&s->Y[d][u + 2 + TOFF]);
                float wj[4]  = {w4.x, w4.y, w4.z, w4.w};
                float ydx[4] = {ydA.x, ydA.z, ydB.x, ydB.z};
                float ydy[4] = {ydA.y, ydA.w, ydB.y, ydB.w};
#pragma unroll
                for (int j = 0; j < 4; j++) {
#pragma unroll
                    for (int k = NTAPS-1; k > 0; k--) { dxx[k]=dxx[k-1]; dyy[k]=dyy[k-1]; }
                    dxx[0] = pk2(ydx[j], ydx[j]);
                    dyy[0] = pk2(ydy[j], ydy[j]);
                    float2 ye = s->Y[e][u + j + 3 + TOFF];
                    u64 sv = mul2(pk2(wj[j], wj[j]), pk2(ye.x, ye.y));
#pragma unroll
                    for (int k = 0; k < NTAPS; k++) {
                        accA[k] = fma2(dxx[k], sv, accA[k]);
                        accB[k] = fma2(dyy[k], sv, accB[k]);
                    }
                }
            }
            {   // remainder u = 596
                const int u = 596;
#pragma unroll
                for (int k = NTAPS-1; k > 0; k--) { dxx[k]=dxx[k-1]; dyy[k]=dyy[k-1]; }
                float2 yd = s->Y[d][u + TOFF];
                dxx[0] = pk2(yd.x, yd.x);
                dyy[0] = pk2(yd.y, yd.y);
                float2 ye = s->Y[e][u + 3 + TOFF];
                float w = s->invp[IOFF + u + 3];
                u64 sv = mul2(pk2(w, w), pk2(ye.x, ye.y));
#pragma unroll
                for (int k = 0; k < NTAPS; k++) {
                    accA[k] = fma2(dxx[k], sv, accA[k]);
                    accB[k] = fma2(dyy[k], sv, accB[k]);
                }
            }
#pragma unroll
            for (int k = 0; k < NTAPS; k++) {
                float2 A = upk2(accA[k]), B = upk2(accB[k]);
                s->P[k][e][d] = make_float2(A.x + B.y, A.y - B.x);
            }
        }
        __syncthreads();

        // ---- weights dead: repurpose invp as ps accumulator (zero it);
        //      regularize R diag. Both covered by LDL's first barrier. ----
        for (int t = tid; t < TT; t += NTHREADS) s->invp[t + IOFF] = 0.f;
        if (tid < KC) s->R[tid][tid].x += EPSV;

        // ---- in-place LDL^H of R: one barrier per column; dinv -> R[j][j].y
        for (int j = 0; j < KC; j++) {
            __syncthreads();                 // column j fully updated
            float djj = s->R[j][j].x;        // broadcast read
            float dinv = 1.0f / fmaxf(djj, 1e-30f);
            if (tid == 0) s->R[j][j].y = dinv;
            for (int i = j + 1 + (tid & 31); i < KC; i += 32) {
                float2 Aij = s->R[i][j];
                float2 Aw = make_float2(Aij.x * dinv, Aij.y * dinv);
                for (int l = j + 1 + (tid >> 5); l <= i; l += 8) {
                    float2 Alj = s->R[l][j];
                    s->R[i][l].x -= Aw.x*Alj.x + Aw.y*Alj.y;
                    s->R[i][l].y -= Aw.y*Alj.x - Aw.x*Alj.y;
                }
            }
        }
        __syncthreads();

        // ---- triangular solves in registers: warp e solves for channel e ----
        {
            int lane = tid & 31, e = tid >> 5;
            float2 x0, x1;
            { int i = lane;      x0 = s->P[i>>3][e][i&7]; }
            if (lane < 8) { int i = lane + 32; x1 = s->P[i>>3][e][i&7]; }
            else x1 = make_float2(0.f, 0.f);
            float dinv0 = s->R[lane][lane].y;
            float dinv1 = (lane < 8) ? s->R[lane+32][lane+32].y : 0.f;

            // forward: unit-lower L y = b
            for (int j = 0; j < KC; j++) {
                int src = j & 31;
                float2 xj = (j < 32) ? shfl2(x0, src) : shfl2(x1, src);
                float dj = s->R[j][j].y;
                float2 t = make_float2(xj.x * dj, xj.y * dj);
                if (lane > j) {
                    float2 L = s->R[lane][j];
                    x0.x -= L.x*t.x - L.y*t.y;
                    x0.y -= L.x*t.y + L.y*t.x;
                }
                if (lane < 8 && lane + 32 > j) {
                    float2 L = s->R[lane+32][j];
                    x1.x -= L.x*t.x - L.y*t.y;
                    x1.y -= L.x*t.y + L.y*t.x;
                }
            }
            // z = D^{-1} y
            x0.x *= dinv0; x0.y *= dinv0;
            x1.x *= dinv1; x1.y *= dinv1;
            // backward: L^H x = z
            for (int j = KC - 1; j >= 1; j--) {
                int src = j & 31;
                float2 xj = (j < 32) ? shfl2(x0, src) : shfl2(x1, src);
                if (lane < j) {
                    float2 A = s->R[j][lane];
                    x0.x -= dinv0 * (A.x*xj.x + A.y*xj.y);
                    x0.y -= dinv0 * (A.x*xj.y - A.y*xj.x);
                }
                if (lane < 8 && lane + 32 < j) {
                    float2 A = s->R[j][lane+32];
                    x1.x -= dinv1 * (A.x*xj.x + A.y*xj.y);
                    x1.y -= dinv1 * (A.x*xj.y - A.y*xj.x);
                }
            }
            // write G_conj: i=(k*8+d) -> G[k][d][e]
            { int i = lane;      s->G[i>>3][i&7][e] = x0; }
            if (lane < 8) { int i = lane + 32; s->G[i>>3][i&7][e] = x1; }
        }
        __syncthreads();

        // ---- reverb: E[e][t] = Y[e][t] - sum_{p,d} G[p][d][e] * Y[d][t-3-p] ----
        // single-pass 19 frames/lane; padded Y -> NO load guards.
        // iter-1: accumulate |E|^2 into invp (ps). iter-2: store E to g_E.
        {
            int lane = tid & 31, e = tid >> 5;
            int t0 = lane * 19;
            float2* Eg = g_E + ((size_t)bf * CC + e) * TT;
            u64 acc[19];
#pragma unroll
            for (int i = 0; i < 19; i++) {
                float2 y = s->Y[e][t0 + i + TOFF];   // pad reads give zeros
                acc[i] = pk2(y.x, y.y);
            }
#pragma unroll
            for (int d = 0; d < CC; d++) {
                u64 gxn[NTAPS], gys[NTAPS];
#pragma unroll
                for (int p = 0; p < NTAPS; p++) {
                    float2 g = s->G[p][d][e];        // broadcast LDS
                    gxn[p] = pk2(-g.x, -g.x);
                    gys[p] = pk2(g.y, -g.y);
                }
                u64 w[NTAPS], ws[NTAPS];
#pragma unroll
                for (int p = 0; p < NTAPS-1; p++) {
                    float2 y = s->Y[d][t0 - 4 - p + TOFF];  // pad-safe
                    w[p]  = pk2(y.x, y.y);
                    ws[p] = pk2(y.y, y.x);
                }
                w[NTAPS-1] = ws[NTAPS-1] = 0ull;
#pragma unroll
                for (int i = 0; i < 19; i++) {
#pragma unroll
                    for (int p = NTAPS-1; p > 0; p--) { w[p]=w[p-1]; ws[p]=ws[p-1]; }
                    float2 y = s->Y[d][t0 + i - 3 + TOFF];  // pad-safe both ends
                    w[0]  = pk2(y.x, y.y);
                    ws[0] = pk2(y.y, y.x);
#pragma unroll
                    for (int p = 0; p < NTAPS; p++) {
                        acc[i] = fma2(gxn[p], w[p],  acc[i]);
                        acc[i] = fma2(gys[p], ws[p], acc[i]);
                    }
                }
            }
            if (it == 0) {
#pragma unroll
                for (int i = 0; i < 19; i++) {
                    int t = t0 + i;
                    if (t < TT) {
                        float2 v = upk2(acc[i]);
                        atomicAdd(&s->invp[t + IOFF], v.x*v.x + v.y*v.y);
                    }
                }
                __syncthreads();    // ps complete before iter-2 power
            } else {
#pragma unroll
                for (int i = 0; i < 19; i++) {
                    int t = t0 + i;
                    if (t < TT) Eg[t] = upk2(acc[i]);
                }
            }
        }
    } // iterations
}

// ---------------------------------------------------------------------------
extern "C" void kernel_launch(void* const* d_in, const int* in_sizes, int n_in,
                              void* d_out, int out_size) {
    const float* re    = (const float*)d_in[0];
    const float* im    = (const float*)d_in[1];
    const int*   ilens = (const int*)d_in[2];
    float* out = (float*)d_out;

    cudaFuncSetAttribute(k_wpe, cudaFuncAttributeMaxDynamicSharedMemorySize,
                         (int)sizeof(WpeSmem));

    dim3 blk(32, 8);
    k_transpose_in<<<dim3((FF+31)/32, (TT+31)/32, BB*CC), blk>>>(re, im);
    k_wpe<<<BB*FF, NTHREADS, sizeof(WpeSmem)>>>();
    k_transpose_out<<<dim3((TT+31)/32, (FF+31)/32, BB*CC), blk>>>(out, ilens);
}